// round 11
// baseline (speedup 1.0000x reference)
#include <cuda_runtime.h>
#include <cstdint>

// ---------------------------------------------------------------------------
// HDCTokenEncoder: out[b,i,d] = item_memory[tok[b,i]][(d - i) mod D] * (1/sqrt(D))
// item_memory entries are exactly +/-1 => row L2 norm == sqrt(D) == 100 exactly,
// so normalization is the constant 0.01f (applied once while staging SMEM).
//
// R11 = R9 (best: coalesced scan, merged barrier, single-row aligned emission)
// + unroll-2 batched-LDS emission. Multiple kernel shapes all converge at
// ~6.0-6.1 TB/s effective writes -- the practical HBM3e pure-write ceiling --
// so this round only shaves issue/ALU overhead in the hot loop.
//
// Classes: y in [0,16) -> (c = y>>2, m = y&3). Block (t, y) handles positions
// i in [512c, 512c+512) with i % 4 == m, across all 8 batches. Each int4 of
// the token array holds exactly one candidate (element m) -> coalesced scan.
// All rows share m = r mod 4 -> staged row is pre-rotated by m:
//   T[d] = 0.01 * row[(d - m) mod D]
// so each output row is a whole-quad rotation: load T[(g - q0) mod D4], store
// at quad g (sector-aligned STG.128 streams), q0 = (r - m)/4.
// ---------------------------------------------------------------------------

#define HDC_D      10000
#define HDC_D4     2500              // D / 4
#define HDC_S      2048              // sequence length (power of two)
#define HDC_V      256
#define NCLASS     16                // 4 chunks x 4 residues
#define CHUNK      512               // positions per chunk (S / 4)
#define CAND_VEC   1024              // int4 candidates per block (8 batches x 128)
#define NTHR       512

template <int OFS>
__device__ __forceinline__ float4 blend(float4 A, float4 B) {
    if (OFS == 0) return A;
    if (OFS == 1) return make_float4(A.y, A.z, A.w, B.x);
    if (OFS == 2) return make_float4(A.z, A.w, B.x, B.y);
    return make_float4(A.w, B.x, B.y, B.z);
}

// Stage T[d] = 0.01 * s[(d - m) mod D]; OFS = (-m) mod 4.
template <int OFS>
__device__ __forceinline__ void stage(const float4* __restrict__ sq,
                                      float4* __restrict__ T4, int m) {
    const float scale = 0.01f;
    for (int g = threadIdx.x; g < HDC_D4; g += NTHR) {
        int s0 = 4 * g - m;
        if (s0 < 0) s0 += HDC_D;
        int qa = s0 >> 2;
        float4 v;
        if (OFS == 0) {
            v = __ldg(&sq[qa]);
        } else {
            int qb = qa + 1;
            if (qb == HDC_D4) qb = 0;
            v = blend<OFS>(__ldg(&sq[qa]), __ldg(&sq[qb]));
        }
        v.x *= scale; v.y *= scale; v.z *= scale; v.w *= scale;
        T4[g] = v;
    }
}

// One row, unroll-2 with batched LDS: out quad g <- T quad (g - q0) mod D4.
__device__ __forceinline__ void emit1(const float4* __restrict__ T4,
                                      float4* __restrict__ dst, int q0) {
    int qa = (int)threadIdx.x - q0;
    if (qa < 0) qa += HDC_D4;
    int g = threadIdx.x;
    // double iterations: (g, g+NTHR) both valid
    for (; g + NTHR < HDC_D4; g += 2 * NTHR) {
        int qb = qa + NTHR;
        if (qb >= HDC_D4) qb -= HDC_D4;
        float4 v0 = T4[qa];              // two independent LDS.128
        float4 v1 = T4[qb];
        __stcs(dst + g, v0);             // two aligned streaming STG.128
        __stcs(dst + g + NTHR, v1);
        qa = qb + NTHR;
        if (qa >= HDC_D4) qa -= HDC_D4;
    }
    if (g < HDC_D4)
        __stcs(dst + g, T4[qa]);
}

__global__ __launch_bounds__(NTHR, 4) void k_encode(const int* __restrict__ tok,
                                                    const float* __restrict__ im,
                                                    float* __restrict__ out) {
    __shared__ float4 T4[HDC_D4];      // 40 KB pre-rotated, pre-scaled row
    __shared__ int    list[CAND_VEC];  // 4 KB: matching flat positions
    __shared__ int    nmatch;

    const int t = blockIdx.x;          // token id
    const int y = blockIdx.y;          // class
    const int c = y >> 2;              // chunk index
    const int m = y & 3;               // shared r mod 4 for all rows here

    if (threadIdx.x == 0) nmatch = 0;
    __syncthreads();

    // Phase 1: coalesced scan (2 LDG.128 per thread).
    // int4 vector q in [0,1024): b = q>>7, local = q&127,
    // candidate position i = 512c + 4*local + m, flat bs = 2048b + i.
    const int4* tok4 = reinterpret_cast<const int4*>(tok);
    const int vbase = c * (CHUNK / 4);   // c * 128
    for (int q = threadIdx.x; q < CAND_VEC; q += NTHR) {
        int b     = q >> 7;
        int local = q & 127;
        int4 vec  = __ldg(&tok4[b * (HDC_S / 4) + vbase + local]);
        int v = (m < 2) ? (m == 0 ? vec.x : vec.y)
                        : (m == 2 ? vec.z : vec.w);
        if (v == t) {
            int k = atomicAdd(&nmatch, 1);
            list[k] = b * HDC_S + c * CHUNK + 4 * local + m;
        }
    }
    // No barrier here: staging is independent of the scan; the single barrier
    // below orders both list[] and T4[] before emission.

    // Phase 2: stage the pre-rotated, pre-scaled row (blend paid once).
    const float4* sq = reinterpret_cast<const float4*>(im + (size_t)t * HDC_D);
    switch ((4 - m) & 3) {
        case 0: stage<0>(sq, T4, m); break;
        case 1: stage<1>(sq, T4, m); break;
        case 2: stage<2>(sq, T4, m); break;
        default: stage<3>(sq, T4, m); break;
    }
    __syncthreads();

    const int n = nmatch;

    // Phase 3: emit rows; each is a whole-quad rotation of T.
    for (int p = 0; p < n; ++p) {
        const int bs = list[p];
        const int q0 = ((bs & (HDC_S - 1)) - m) >> 2;   // whole-quad rotation
        emit1(T4, reinterpret_cast<float4*>(out + (size_t)bs * HDC_D), q0);
    }
}

extern "C" void kernel_launch(void* const* d_in, const int* in_sizes, int n_in,
                              void* d_out, int out_size) {
    const int*   tok = (const int*)d_in[0];     // (B, S) int32
    const float* im  = (const float*)d_in[1];   // (V, D) float32
    float*       out = (float*)d_out;           // (B, S, D) float32
    (void)in_sizes; (void)n_in; (void)out_size;

    dim3 grid(HDC_V, NCLASS);
    k_encode<<<grid, NTHR>>>(tok, im, out);
}